// round 1
// baseline (speedup 1.0000x reference)
#include <cuda_runtime.h>
#include <math.h>
#include <float.h>

#define BATCH 16
#define NPTS  2048
#define DIM   64
#define SPLIT 16
#define ROWS_PER (NPTS / SPLIT)   // 128
#define STR 66                    // smem row stride (even -> float2 aligned, 2-way conflicts on col access)
#define MAXSWEEP 16
#define MINSWEEP 5

// scratch for partial maxima: 16 * 16 * 4096 * 4B = 4 MB
__device__ float g_partial[BATCH][SPLIT][DIM * DIM];

// ---------------------------------------------------------------------------
// Kernel 1: partial max of outer products over a 128-row chunk of n
// grid = (SPLIT, BATCH), 256 threads, each thread owns a 4x4 (i,j) tile
// ---------------------------------------------------------------------------
__global__ void __launch_bounds__(256) sop_partial_max(const float* __restrict__ x) {
    const int b = blockIdx.y;
    const int c = blockIdx.x;
    __shared__ float xs[ROWS_PER][DIM];   // 32 KB

    const float* xp = x + ((size_t)b * NPTS + (size_t)c * ROWS_PER) * DIM;
    const int tid = threadIdx.x;

    // coalesced float4 load of the chunk
    for (int e = tid * 4; e < ROWS_PER * DIM; e += 256 * 4) {
        float4 v = *(const float4*)(xp + e);
        *(float4*)(&xs[0][0] + e) = v;
    }
    __syncthreads();

    const int ti = (tid >> 4) * 4;   // i0
    const int tj = (tid & 15) * 4;   // j0
    float acc[4][4];
#pragma unroll
    for (int a = 0; a < 4; a++)
#pragma unroll
        for (int bb = 0; bb < 4; bb++) acc[a][bb] = -FLT_MAX;

#pragma unroll 4
    for (int n = 0; n < ROWS_PER; n++) {
        float4 vi = *(const float4*)&xs[n][ti];
        float4 vj = *(const float4*)&xs[n][tj];
        float fi[4] = {vi.x, vi.y, vi.z, vi.w};
        float fj[4] = {vj.x, vj.y, vj.z, vj.w};
#pragma unroll
        for (int a = 0; a < 4; a++)
#pragma unroll
            for (int bb = 0; bb < 4; bb++)
                acc[a][bb] = fmaxf(acc[a][bb], fi[a] * fj[bb]);
    }

    float* outp = g_partial[b][c];
#pragma unroll
    for (int a = 0; a < 4; a++) {
        float4 v = make_float4(acc[a][0], acc[a][1], acc[a][2], acc[a][3]);
        *(float4*)(outp + (ti + a) * DIM + tj) = v;
    }
}

// ---------------------------------------------------------------------------
// block reduce sum (1024 threads / 32 warps)
// ---------------------------------------------------------------------------
__device__ __forceinline__ float block_reduce_sum(float v, float* red, int tid) {
    __syncthreads();  // protect 'red' from prior use
#pragma unroll
    for (int o = 16; o; o >>= 1) v += __shfl_down_sync(0xffffffffu, v, o);
    if ((tid & 31) == 0) red[tid >> 5] = v;
    __syncthreads();
    if (tid < 32) {
        float w = red[tid];
#pragma unroll
        for (int o = 16; o; o >>= 1) w += __shfl_down_sync(0xffffffffu, w, o);
        if (tid == 0) red[0] = w;
    }
    __syncthreads();
    return red[0];
}

// ---------------------------------------------------------------------------
// Kernel 2: per-batch: reduce partial maxima -> symmetric A; parallel Jacobi
// eigendecomposition; sq = Q * sign(L)*sqrt(|L|) * Q^T; L2-normalize; write.
// grid = BATCH, 1024 threads.
// ---------------------------------------------------------------------------
__global__ void __launch_bounds__(1024) sop_eig_kernel(float* __restrict__ out) {
    const int b = blockIdx.x;
    const int tid = threadIdx.x;

    __shared__ float As[DIM * STR];
    __shared__ float Qts[DIM * STR];
    __shared__ float cs_c[32], cs_s[32];
    __shared__ int   cs_p[32], cs_q[32];
    __shared__ float red[32];
    __shared__ float gs[DIM];

    // ---- reduce partials into A, init Qt = I ----
    float frloc = 0.f;
    for (int e = tid; e < DIM * DIM; e += 1024) {
        const int i = e >> 6, j = e & 63;
        float m = -FLT_MAX;
#pragma unroll
        for (int c = 0; c < SPLIT; c++) m = fmaxf(m, g_partial[b][c][e]);
        As[i * STR + j] = m;
        Qts[i * STR + j] = (i == j) ? 1.0f : 0.0f;
        frloc += m * m;
    }
    const float frob2 = block_reduce_sum(frloc, red, tid) + 1e-30f;

    // ---- cyclic Jacobi sweeps, tournament ordering ----
    for (int sweep = 0; sweep < MAXSWEEP; sweep++) {
        for (int r = 0; r < 63; r++) {
            // rotation params: one thread per pair
            if (tid < 32) {
                int p, q;
                if (tid == 0) { p = 63; q = r; }
                else {
                    p = (r + tid) % 63;
                    q = (r + 63 - tid) % 63;
                }
                const float app = As[p * STR + p];
                const float aqq = As[q * STR + q];
                const float apq = As[p * STR + q];
                float cc = 1.f, ss = 0.f;
                if (fabsf(apq) > 1e-20f) {
                    const float tau = (aqq - app) / (2.f * apq);
                    const float t = copysignf(1.f, tau) /
                                    (fabsf(tau) + sqrtf(1.f + tau * tau));
                    cc = rsqrtf(1.f + t * t);
                    ss = t * cc;
                }
                cs_c[tid] = cc; cs_s[tid] = ss; cs_p[tid] = p; cs_q[tid] = q;
            }
            __syncthreads();

            // row phase: A <- J^T A   (rows p,q disjoint across pairs)
            {
                const int pair = tid >> 5;
                const int kk = (tid & 31) * 2;
                const int p = cs_p[pair], q = cs_q[pair];
                const float c = cs_c[pair], s = cs_s[pair];
                float2 ap = *(float2*)&As[p * STR + kk];
                float2 aq = *(float2*)&As[q * STR + kk];
                *(float2*)&As[p * STR + kk] = make_float2(c * ap.x - s * aq.x,
                                                          c * ap.y - s * aq.y);
                *(float2*)&As[q * STR + kk] = make_float2(s * ap.x + c * aq.x,
                                                          s * ap.y + c * aq.y);
            }
            __syncthreads();

            // col phase: A <- A J, and Qt <- J^T Qt (disjoint arrays, one barrier)
            {
                const int pair = tid >> 5;
                const int k = (tid & 31);
                const int p = cs_p[pair], q = cs_q[pair];
                const float c = cs_c[pair], s = cs_s[pair];
#pragma unroll
                for (int kk = k; kk < DIM; kk += 32) {
                    const float akp = As[kk * STR + p];
                    const float akq = As[kk * STR + q];
                    As[kk * STR + p] = c * akp - s * akq;
                    As[kk * STR + q] = s * akp + c * akq;
                }
                const int kk2 = k * 2;
                float2 qp = *(float2*)&Qts[p * STR + kk2];
                float2 qq = *(float2*)&Qts[q * STR + kk2];
                *(float2*)&Qts[p * STR + kk2] = make_float2(c * qp.x - s * qq.x,
                                                            c * qp.y - s * qq.y);
                *(float2*)&Qts[q * STR + kk2] = make_float2(s * qp.x + c * qq.x,
                                                            s * qp.y + c * qq.y);
            }
            __syncthreads();
        }

        // convergence check (off-diagonal Frobenius^2)
        if (sweep >= MINSWEEP - 1) {
            float off = 0.f;
            for (int e = tid; e < DIM * DIM; e += 1024) {
                const int i = e >> 6, j = e & 63;
                const float v = As[i * STR + j];
                off += (i != j) ? v * v : 0.f;
            }
            const float offt = block_reduce_sum(off, red, tid);
            if (offt < 1e-13f * frob2) break;
        }
    }

    // ---- g(lambda) = sign(l)*sqrt(|l|) ----
    if (tid < DIM) {
        const float lam = As[tid * STR + tid];
        gs[tid] = copysignf(sqrtf(fabsf(lam)), lam);
    }
    __syncthreads();

    // P[k][i] = g_k * Qt[k][i] (overwrite A)
    for (int e = tid; e < DIM * DIM; e += 1024) {
        const int k = e >> 6, i = e & 63;
        As[k * STR + i] = gs[k] * Qts[k * STR + i];
    }
    __syncthreads();

    // sq[i][j] = sum_k P[k][i] * Qt[k][j], thread owns (i, j0..j0+3)
    const int i = tid >> 4;
    const int j0 = (tid & 15) * 4;
    float a0 = 0.f, a1 = 0.f, a2 = 0.f, a3 = 0.f;
#pragma unroll 4
    for (int k = 0; k < DIM; k++) {
        const float pki = As[k * STR + i];
        float2 qa = *(float2*)&Qts[k * STR + j0];
        float2 qb = *(float2*)&Qts[k * STR + j0 + 2];
        a0 += pki * qa.x;
        a1 += pki * qa.y;
        a2 += pki * qb.x;
        a3 += pki * qb.y;
    }

    // L2 normalize over all 4096 entries
    const float ssq = a0 * a0 + a1 * a1 + a2 * a2 + a3 * a3;
    const float total = block_reduce_sum(ssq, red, tid);
    const float scale = 1.f / fmaxf(sqrtf(total), 1e-12f);

    float4 v = make_float4(a0 * scale, a1 * scale, a2 * scale, a3 * scale);
    *(float4*)(out + (size_t)b * (DIM * DIM) + i * DIM + j0) = v;
}

// ---------------------------------------------------------------------------
extern "C" void kernel_launch(void* const* d_in, const int* in_sizes, int n_in,
                              void* d_out, int out_size) {
    const float* x = (const float*)d_in[0];
    float* out = (float*)d_out;

    sop_partial_max<<<dim3(SPLIT, BATCH), 256>>>(x);
    sop_eig_kernel<<<BATCH, 1024>>>(out);
}

// round 2
// speedup vs baseline: 2.5454x; 2.5454x over previous
#include <cuda_runtime.h>
#include <math.h>
#include <float.h>

#define BATCH 16
#define NPTS  2048
#define DIM   64
#define SPLIT 16
#define ROWS_PER (NPTS / SPLIT)   // 128
#define STR 66                    // smem row stride (float2-aligned; 2-way conflicts on column access)
#define MAXSWEEP 10
#define CHECK_FROM 3              // start convergence checks after sweep index >= 3 (4 sweeps done)

// scratch for partial maxima: 16 * 16 * 4096 * 4B = 4 MB
__device__ float g_partial[BATCH][SPLIT][DIM * DIM];

// ---------------------------------------------------------------------------
// Kernel 1: partial max of outer products over a 128-row chunk of n
// grid = (SPLIT, BATCH), 256 threads, each thread owns a 4x4 (i,j) tile
// ---------------------------------------------------------------------------
__global__ void __launch_bounds__(256) sop_partial_max(const float* __restrict__ x) {
    const int b = blockIdx.y;
    const int c = blockIdx.x;
    __shared__ float xs[ROWS_PER][DIM];   // 32 KB

    const float* xp = x + ((size_t)b * NPTS + (size_t)c * ROWS_PER) * DIM;
    const int tid = threadIdx.x;

    for (int e = tid * 4; e < ROWS_PER * DIM; e += 256 * 4) {
        float4 v = *(const float4*)(xp + e);
        *(float4*)(&xs[0][0] + e) = v;
    }
    __syncthreads();

    const int ti = (tid >> 4) * 4;
    const int tj = (tid & 15) * 4;
    float acc[4][4];
#pragma unroll
    for (int a = 0; a < 4; a++)
#pragma unroll
        for (int bb = 0; bb < 4; bb++) acc[a][bb] = -FLT_MAX;

#pragma unroll 4
    for (int n = 0; n < ROWS_PER; n++) {
        float4 vi = *(const float4*)&xs[n][ti];
        float4 vj = *(const float4*)&xs[n][tj];
        float fi[4] = {vi.x, vi.y, vi.z, vi.w};
        float fj[4] = {vj.x, vj.y, vj.z, vj.w};
#pragma unroll
        for (int a = 0; a < 4; a++)
#pragma unroll
            for (int bb = 0; bb < 4; bb++)
                acc[a][bb] = fmaxf(acc[a][bb], fi[a] * fj[bb]);
    }

    float* outp = g_partial[b][c];
#pragma unroll
    for (int a = 0; a < 4; a++) {
        float4 v = make_float4(acc[a][0], acc[a][1], acc[a][2], acc[a][3]);
        *(float4*)(outp + (ti + a) * DIM + tj) = v;
    }
}

// ---------------------------------------------------------------------------
// block reduce sum (1024 threads / 32 warps)
// ---------------------------------------------------------------------------
__device__ __forceinline__ float block_reduce_sum(float v, float* red, int tid) {
    __syncthreads();
#pragma unroll
    for (int o = 16; o; o >>= 1) v += __shfl_down_sync(0xffffffffu, v, o);
    if ((tid & 31) == 0) red[tid >> 5] = v;
    __syncthreads();
    if (tid < 32) {
        float w = red[tid];
#pragma unroll
        for (int o = 16; o; o >>= 1) w += __shfl_down_sync(0xffffffffu, w, o);
        if (tid == 0) red[0] = w;
    }
    __syncthreads();
    return red[0];
}

// ---------------------------------------------------------------------------
// Kernel 2: per-batch eigendecomposition via parallel cyclic Jacobi.
// Warp w == pair w. Rotation params computed redundantly per-lane (broadcast
// LDS reads), so a round is: [param+row phase] bar [col+Qt phase] bar.
// grid = BATCH, 1024 threads.
// ---------------------------------------------------------------------------
__global__ void __launch_bounds__(1024) sop_eig_kernel(float* __restrict__ out) {
    const int b = blockIdx.x;
    const int tid = threadIdx.x;
    const int warp = tid >> 5;
    const int lane = tid & 31;

    __shared__ float As[DIM * STR];
    __shared__ float Qts[DIM * STR];
    __shared__ float red[32];
    __shared__ float gs[DIM];

    // ---- reduce partials into A, init Qt = I ----
    float frloc = 0.f;
    for (int e = tid; e < DIM * DIM; e += 1024) {
        const int i = e >> 6, j = e & 63;
        float m = -FLT_MAX;
#pragma unroll
        for (int c = 0; c < SPLIT; c++) m = fmaxf(m, g_partial[b][c][e]);
        As[i * STR + j] = m;
        Qts[i * STR + j] = (i == j) ? 1.0f : 0.0f;
        frloc += m * m;
    }
    const float frob2 = block_reduce_sum(frloc, red, tid) + 1e-30f;
    // block_reduce_sum ends with __syncthreads -> As fully visible

    // ---- cyclic Jacobi sweeps, tournament ordering ----
    for (int sweep = 0; sweep < MAXSWEEP; sweep++) {
        for (int r = 0; r < 63; r++) {
            // pair (p,q) for this warp this round
            int p, q;
            if (warp == 0) { p = 63; q = r; }
            else {
                p = (r + warp) % 63;
                q = (r + 63 - warp) % 63;
            }

            // rotation params: every lane reads the same 3 smem cells
            // (broadcast, conflict-free) and computes redundantly.
            const float app = As[p * STR + p];
            const float aqq = As[q * STR + q];
            const float apq = As[p * STR + q];
            float c = 1.f, s = 0.f;
            if (fabsf(apq) > 1e-20f) {
                const float tau = (aqq - app) / (2.f * apq);
                const float t = copysignf(1.f, tau) /
                                (fabsf(tau) + sqrtf(1.f + tau * tau));
                c = rsqrtf(1.f + t * t);
                s = t * c;
            }

            // row phase: A <- J^T A (rows p,q; disjoint across warps)
            {
                const int kk = lane * 2;
                float2 ap = *(float2*)&As[p * STR + kk];
                float2 aq = *(float2*)&As[q * STR + kk];
                *(float2*)&As[p * STR + kk] = make_float2(c * ap.x - s * aq.x,
                                                          c * ap.y - s * aq.y);
                *(float2*)&As[q * STR + kk] = make_float2(s * ap.x + c * aq.x,
                                                          s * ap.y + c * aq.y);
            }
            __syncthreads();

            // col phase: A <- A J ; Qt <- J^T Qt
            {
#pragma unroll
                for (int kk = lane; kk < DIM; kk += 32) {
                    const float akp = As[kk * STR + p];
                    const float akq = As[kk * STR + q];
                    As[kk * STR + p] = c * akp - s * akq;
                    As[kk * STR + q] = s * akp + c * akq;
                }
                const int kk2 = lane * 2;
                float2 qp = *(float2*)&Qts[p * STR + kk2];
                float2 qq = *(float2*)&Qts[q * STR + kk2];
                *(float2*)&Qts[p * STR + kk2] = make_float2(c * qp.x - s * qq.x,
                                                            c * qp.y - s * qq.y);
                *(float2*)&Qts[q * STR + kk2] = make_float2(s * qp.x + c * qq.x,
                                                            s * qp.y + c * qq.y);
            }
            __syncthreads();
        }

        // convergence check: off-diagonal Frobenius^2 vs realistic fp32 plateau
        if (sweep >= CHECK_FROM) {
            float off = 0.f;
            for (int e = tid; e < DIM * DIM; e += 1024) {
                const int i = e >> 6, j = e & 63;
                const float v = As[i * STR + j];
                off += (i != j) ? v * v : 0.f;
            }
            const float offt = block_reduce_sum(off, red, tid);
            if (offt < 1e-9f * frob2) break;
        }
    }

    // ---- g(lambda) = sign(l)*sqrt(|l|) ----
    __syncthreads();
    if (tid < DIM) {
        const float lam = As[tid * STR + tid];
        gs[tid] = copysignf(sqrtf(fabsf(lam)), lam);
    }
    __syncthreads();

    // P[k][i] = g_k * Qt[k][i] (overwrite A)
    for (int e = tid; e < DIM * DIM; e += 1024) {
        const int k = e >> 6, i = e & 63;
        As[k * STR + i] = gs[k] * Qts[k * STR + i];
    }
    __syncthreads();

    // sq[i][j] = sum_k P[k][i] * Qt[k][j], thread owns (i, j0..j0+3)
    const int i = tid >> 4;
    const int j0 = (tid & 15) * 4;
    float a0 = 0.f, a1 = 0.f, a2 = 0.f, a3 = 0.f;
#pragma unroll 4
    for (int k = 0; k < DIM; k++) {
        const float pki = As[k * STR + i];
        float2 qa = *(float2*)&Qts[k * STR + j0];
        float2 qb = *(float2*)&Qts[k * STR + j0 + 2];
        a0 += pki * qa.x;
        a1 += pki * qa.y;
        a2 += pki * qb.x;
        a3 += pki * qb.y;
    }

    // L2 normalize over all 4096 entries
    const float ssq = a0 * a0 + a1 * a1 + a2 * a2 + a3 * a3;
    const float total = block_reduce_sum(ssq, red, tid);
    const float scale = 1.f / fmaxf(sqrtf(total), 1e-12f);

    float4 v = make_float4(a0 * scale, a1 * scale, a2 * scale, a3 * scale);
    *(float4*)(out + (size_t)b * (DIM * DIM) + i * DIM + j0) = v;
}

// ---------------------------------------------------------------------------
extern "C" void kernel_launch(void* const* d_in, const int* in_sizes, int n_in,
                              void* d_out, int out_size) {
    const float* x = (const float*)d_in[0];
    float* out = (float*)d_out;

    sop_partial_max<<<dim3(SPLIT, BATCH), 256>>>(x);
    sop_eig_kernel<<<BATCH, 1024>>>(out);
}

// round 3
// speedup vs baseline: 2.8971x; 1.1382x over previous
#include <cuda_runtime.h>
#include <math.h>
#include <float.h>

#define BATCH 16
#define NPTS  2048
#define DIM   64
#define SPLIT 16
#define ROWS_PER (NPTS / SPLIT)   // 128
#define STR 66
#define MAXSWEEP 10
#define CHECK_FROM 3

#define EIG_SMEM_FLOATS (3 * DIM * STR)
#define EIG_SMEM_BYTES  (EIG_SMEM_FLOATS * 4)

// scratch for partial maxima: 16 * 16 * 4096 * 4B = 4 MB
__device__ float g_partial[BATCH][SPLIT][DIM * DIM];

// ---------------------------------------------------------------------------
// Kernel 1: partial max of outer products over a 128-row chunk of n
// ---------------------------------------------------------------------------
__global__ void __launch_bounds__(256) sop_partial_max(const float* __restrict__ x) {
    const int b = blockIdx.y;
    const int c = blockIdx.x;
    __shared__ float xs[ROWS_PER][DIM];

    const float* xp = x + ((size_t)b * NPTS + (size_t)c * ROWS_PER) * DIM;
    const int tid = threadIdx.x;

    for (int e = tid * 4; e < ROWS_PER * DIM; e += 256 * 4) {
        float4 v = *(const float4*)(xp + e);
        *(float4*)(&xs[0][0] + e) = v;
    }
    __syncthreads();

    const int ti = (tid >> 4) * 4;
    const int tj = (tid & 15) * 4;
    float acc[4][4];
#pragma unroll
    for (int a = 0; a < 4; a++)
#pragma unroll
        for (int bb = 0; bb < 4; bb++) acc[a][bb] = -FLT_MAX;

#pragma unroll 4
    for (int n = 0; n < ROWS_PER; n++) {
        float4 vi = *(const float4*)&xs[n][ti];
        float4 vj = *(const float4*)&xs[n][tj];
        float fi[4] = {vi.x, vi.y, vi.z, vi.w};
        float fj[4] = {vj.x, vj.y, vj.z, vj.w};
#pragma unroll
        for (int a = 0; a < 4; a++)
#pragma unroll
            for (int bb = 0; bb < 4; bb++)
                acc[a][bb] = fmaxf(acc[a][bb], fi[a] * fj[bb]);
    }

    float* outp = g_partial[b][c];
#pragma unroll
    for (int a = 0; a < 4; a++) {
        float4 v = make_float4(acc[a][0], acc[a][1], acc[a][2], acc[a][3]);
        *(float4*)(outp + (ti + a) * DIM + tj) = v;
    }
}

// ---------------------------------------------------------------------------
__device__ __forceinline__ float block_reduce_sum(float v, float* red, int tid) {
    __syncthreads();
#pragma unroll
    for (int o = 16; o; o >>= 1) v += __shfl_down_sync(0xffffffffu, v, o);
    if ((tid & 31) == 0) red[tid >> 5] = v;
    __syncthreads();
    if (tid < 32) {
        float w = red[tid];
#pragma unroll
        for (int o = 16; o; o >>= 1) w += __shfl_down_sync(0xffffffffu, w, o);
        if (tid == 0) red[0] = w;
    }
    __syncthreads();
    return red[0];
}

// tournament pairing for round r, pair index j  (p > set/any order, consistent)
__device__ __forceinline__ void pair_of(int r, int j, int* p, int* q) {
    if (j == 0) { *p = 63; *q = r; }
    else {
        *p = (r + j) % 63;
        *q = (r + 63 - j) % 63;
    }
}

// ---------------------------------------------------------------------------
// Kernel 2: per-batch eigendecomposition, one barrier per Jacobi round.
// Warp w owns rows (p_w,q_w); lane j owns columns (p_j,q_j) -> 2x2 block.
// A ping-pong buffered (cross-warp param reads), Qt single buffered.
// grid = BATCH, 1024 threads, dynamic smem.
// ---------------------------------------------------------------------------
__global__ void __launch_bounds__(1024) sop_eig_kernel(float* __restrict__ out) {
    extern __shared__ float dsm[];
    float* Abuf0 = dsm;
    float* Abuf1 = dsm + DIM * STR;
    float* Qts   = dsm + 2 * DIM * STR;

    __shared__ float red[32];
    __shared__ float gs[DIM];

    const int b = blockIdx.x;
    const int tid = threadIdx.x;
    const int warp = tid >> 5;
    const int lane = tid & 31;

    // ---- reduce partials into A0, init Qt = I ----
    float frloc = 0.f;
    for (int e = tid; e < DIM * DIM; e += 1024) {
        const int i = e >> 6, j = e & 63;
        float m = -FLT_MAX;
#pragma unroll
        for (int c = 0; c < SPLIT; c++) m = fmaxf(m, g_partial[b][c][e]);
        Abuf0[i * STR + j] = m;
        Qts[i * STR + j] = (i == j) ? 1.0f : 0.0f;
        frloc += m * m;
    }
    const float frob2 = block_reduce_sum(frloc, red, tid) + 1e-30f;
    // ends with __syncthreads -> A0/Qt visible

    int cur = 0;

    for (int sweep = 0; sweep < MAXSWEEP; sweep++) {
        for (int r = 0; r < 63; r++) {
            const float* A  = cur ? Abuf1 : Abuf0;
            float*       An = cur ? Abuf0 : Abuf1;

            int pl, ql; pair_of(r, lane, &pl, &ql);   // this lane's column pair
            int pw, qw; pair_of(r, warp, &pw, &qw);   // this warp's row pair

            // params for pair 'lane' (redundant across warps; 3 MUFU/warp)
            const float app = A[pl * STR + pl];
            const float aqq = A[ql * STR + ql];
            const float apq = A[pl * STR + ql];
            float c = 1.f, s = 0.f;
            if (fabsf(apq) > 1e-20f) {
                const float tau = __fdividef(aqq - app, 2.f * apq);
                const float t = copysignf(1.f, tau) /
                                (fabsf(tau) + sqrtf(1.f + tau * tau));
                c = __frsqrt_rn(1.f + t * t);
                s = t * c;
            }

            // own-row params from lane index == warp id
            const float cw = __shfl_sync(0xffffffffu, c, warp);
            const float sw = __shfl_sync(0xffffffffu, s, warp);

            // fused two-sided update of the 2x2 block (rows pw,qw / cols pl,ql)
            const float a_pp = A[pw * STR + pl];
            const float a_pq = A[pw * STR + ql];
            const float a_qp = A[qw * STR + pl];
            const float a_qq = A[qw * STR + ql];

            const float rp_p = cw * a_pp - sw * a_qp;   // (J^T A)[pw][pl]
            const float rp_q = cw * a_pq - sw * a_qq;   // (J^T A)[pw][ql]
            const float rq_p = sw * a_pp + cw * a_qp;   // (J^T A)[qw][pl]
            const float rq_q = sw * a_pq + cw * a_qq;   // (J^T A)[qw][ql]

            An[pw * STR + pl] = c * rp_p - s * rp_q;
            An[pw * STR + ql] = s * rp_p + c * rp_q;
            An[qw * STR + pl] = c * rq_p - s * rq_q;
            An[qw * STR + ql] = s * rq_p + c * rq_q;

            // Qt <- J^T Qt (rows pw,qw; warp-local, single buffer)
            {
                const int kk = lane * 2;
                float2 qp = *(float2*)&Qts[pw * STR + kk];
                float2 qq = *(float2*)&Qts[qw * STR + kk];
                *(float2*)&Qts[pw * STR + kk] = make_float2(cw * qp.x - sw * qq.x,
                                                            cw * qp.y - sw * qq.y);
                *(float2*)&Qts[qw * STR + kk] = make_float2(sw * qp.x + cw * qq.x,
                                                            sw * qp.y + cw * qq.y);
            }

            __syncthreads();
            cur ^= 1;
        }

        // convergence check on current buffer
        if (sweep >= CHECK_FROM) {
            const float* A = cur ? Abuf1 : Abuf0;
            float off = 0.f;
            for (int e = tid; e < DIM * DIM; e += 1024) {
                const int i = e >> 6, j = e & 63;
                const float v = A[i * STR + j];
                off += (i != j) ? v * v : 0.f;
            }
            const float offt = block_reduce_sum(off, red, tid);
            if (offt < 3e-8f * frob2) break;
        }
    }

    const float* Acur = cur ? Abuf1 : Abuf0;
    float*       Psp  = cur ? Abuf0 : Abuf1;   // spare buffer for P

    // ---- g(lambda) = sign(l)*sqrt(|l|) ----
    __syncthreads();
    if (tid < DIM) {
        const float lam = Acur[tid * STR + tid];
        gs[tid] = copysignf(sqrtf(fabsf(lam)), lam);
    }
    __syncthreads();

    // P[k][i] = g_k * Qt[k][i]
    for (int e = tid; e < DIM * DIM; e += 1024) {
        const int k = e >> 6, i = e & 63;
        Psp[k * STR + i] = gs[k] * Qts[k * STR + i];
    }
    __syncthreads();

    // sq[i][j] = sum_k P[k][i] * Qt[k][j], thread owns (i, j0..j0+3)
    const int i = tid >> 4;
    const int j0 = (tid & 15) * 4;
    float a0 = 0.f, a1 = 0.f, a2 = 0.f, a3 = 0.f;
#pragma unroll 4
    for (int k = 0; k < DIM; k++) {
        const float pki = Psp[k * STR + i];
        float2 qa = *(float2*)&Qts[k * STR + j0];
        float2 qb = *(float2*)&Qts[k * STR + j0 + 2];
        a0 += pki * qa.x;
        a1 += pki * qa.y;
        a2 += pki * qb.x;
        a3 += pki * qb.y;
    }

    // L2 normalize over all 4096 entries
    const float ssq = a0 * a0 + a1 * a1 + a2 * a2 + a3 * a3;
    const float total = block_reduce_sum(ssq, red, tid);
    const float scale = 1.f / fmaxf(sqrtf(total), 1e-12f);

    float4 v = make_float4(a0 * scale, a1 * scale, a2 * scale, a3 * scale);
    *(float4*)(out + (size_t)b * (DIM * DIM) + i * DIM + j0) = v;
}

// ---------------------------------------------------------------------------
extern "C" void kernel_launch(void* const* d_in, const int* in_sizes, int n_in,
                              void* d_out, int out_size) {
    const float* x = (const float*)d_in[0];
    float* out = (float*)d_out;

    cudaFuncSetAttribute(sop_eig_kernel,
                         cudaFuncAttributeMaxDynamicSharedMemorySize,
                         EIG_SMEM_BYTES);

    sop_partial_max<<<dim3(SPLIT, BATCH), 256>>>(x);
    sop_eig_kernel<<<BATCH, 1024, EIG_SMEM_BYTES>>>(out);
}

// round 4
// speedup vs baseline: 2.9521x; 1.0190x over previous
#include <cuda_runtime.h>
#include <math.h>
#include <float.h>

#define BATCH 16
#define NPTS  2048
#define DIM   64
#define SPLIT 16
#define ROWS_PER (NPTS / SPLIT)   // 128
#define STR 66
#define MAXSWEEP 9
#define CHECK_FROM 2              // check convergence after sweep index >= 2 (3 sweeps done)

#define EIG_SMEM_FLOATS (3 * DIM * STR)
#define EIG_SMEM_BYTES  (EIG_SMEM_FLOATS * 4)

// scratch for partial maxima: 16 * 16 * 4096 * 4B = 4 MB
__device__ float g_partial[BATCH][SPLIT][DIM * DIM];

// ---------------------------------------------------------------------------
// Kernel 1: partial max of outer products over a 128-row chunk of n
// ---------------------------------------------------------------------------
__global__ void __launch_bounds__(256) sop_partial_max(const float* __restrict__ x) {
    const int b = blockIdx.y;
    const int c = blockIdx.x;
    __shared__ float xs[ROWS_PER][DIM];

    const float* xp = x + ((size_t)b * NPTS + (size_t)c * ROWS_PER) * DIM;
    const int tid = threadIdx.x;

    for (int e = tid * 4; e < ROWS_PER * DIM; e += 256 * 4) {
        float4 v = *(const float4*)(xp + e);
        *(float4*)(&xs[0][0] + e) = v;
    }
    __syncthreads();

    const int ti = (tid >> 4) * 4;
    const int tj = (tid & 15) * 4;
    float acc[4][4];
#pragma unroll
    for (int a = 0; a < 4; a++)
#pragma unroll
        for (int bb = 0; bb < 4; bb++) acc[a][bb] = -FLT_MAX;

#pragma unroll 4
    for (int n = 0; n < ROWS_PER; n++) {
        float4 vi = *(const float4*)&xs[n][ti];
        float4 vj = *(const float4*)&xs[n][tj];
        float fi[4] = {vi.x, vi.y, vi.z, vi.w};
        float fj[4] = {vj.x, vj.y, vj.z, vj.w};
#pragma unroll
        for (int a = 0; a < 4; a++)
#pragma unroll
            for (int bb = 0; bb < 4; bb++)
                acc[a][bb] = fmaxf(acc[a][bb], fi[a] * fj[bb]);
    }

    float* outp = g_partial[b][c];
#pragma unroll
    for (int a = 0; a < 4; a++) {
        float4 v = make_float4(acc[a][0], acc[a][1], acc[a][2], acc[a][3]);
        *(float4*)(outp + (ti + a) * DIM + tj) = v;
    }
}

// ---------------------------------------------------------------------------
__device__ __forceinline__ float block_reduce_sum(float v, float* red, int tid) {
    __syncthreads();
#pragma unroll
    for (int o = 16; o; o >>= 1) v += __shfl_down_sync(0xffffffffu, v, o);
    if ((tid & 31) == 0) red[tid >> 5] = v;
    __syncthreads();
    if (tid < 32) {
        float w = red[tid];
#pragma unroll
        for (int o = 16; o; o >>= 1) w += __shfl_down_sync(0xffffffffu, w, o);
        if (tid == 0) red[0] = w;
    }
    __syncthreads();
    return red[0];
}

// ---------------------------------------------------------------------------
// Kernel 2: per-batch eigendecomposition, one barrier per Jacobi round.
// Warp w owns rows (p_w,q_w); lane j owns columns (p_j,q_j) -> 2x2 block.
// Incremental tournament indices (all advance +1 mod 63 per round).
// grid = BATCH, 1024 threads, dynamic smem.
// ---------------------------------------------------------------------------
__global__ void __launch_bounds__(1024) sop_eig_kernel(float* __restrict__ out) {
    extern __shared__ float dsm[];
    float* Abuf0 = dsm;
    float* Abuf1 = dsm + DIM * STR;
    float* Qts   = dsm + 2 * DIM * STR;

    __shared__ float red[32];
    __shared__ float gs[DIM];

    const int b = blockIdx.x;
    const int tid = threadIdx.x;
    const int warp = tid >> 5;
    const int lane = tid & 31;

    // ---- reduce partials into A0, init Qt = I ----
    float frloc = 0.f;
    for (int e = tid; e < DIM * DIM; e += 1024) {
        const int i = e >> 6, j = e & 63;
        float m = -FLT_MAX;
#pragma unroll
        for (int c = 0; c < SPLIT; c++) m = fmaxf(m, g_partial[b][c][e]);
        Abuf0[i * STR + j] = m;
        Qts[i * STR + j] = (i == j) ? 1.0f : 0.0f;
        frloc += m * m;
    }
    const float frob2 = block_reduce_sum(frloc, red, tid) + 1e-30f;
    // ends with __syncthreads -> A0/Qt visible

    // ---- persistent tournament indices for this lane's pair ----
    int pl, ql;
    if (lane == 0) { pl = 63; ql = 0; }
    else           { pl = lane; ql = 63 - lane; }
    int plS = pl * STR;
    int qlS = ql * STR;

    int cur = 0;
    float* bufs[2] = {Abuf0, Abuf1};

    for (int sweep = 0; sweep < MAXSWEEP; sweep++) {
        for (int r = 0; r < 63; r++) {
            const float* A  = bufs[cur];
            float*       An = bufs[cur ^ 1];

            // ---- rotation params for pair 'lane' (2 MUFU total) ----
            const float app = A[plS + pl];
            const float aqq = A[qlS + ql];
            const float apq = A[plS + ql];
            const float d = aqq - app;
            const float g = apq + apq;
            const float rr = fmaf(d, d, g * g);
            const float ir = __frsqrt_rn(rr);
            const float xv = fabsf(d) * ir;
            const float yv = fmaf(0.5f, xv, 0.5f);
            const float ic = __frsqrt_rn(yv);
            float c = yv * ic;
            float s = 0.5f * g * ir * ic;
            s = __int_as_float(__float_as_int(s) ^
                               (__float_as_int(d) & 0x80000000));
            if (rr < 1e-40f) { c = 1.f; s = 0.f; }   // selects

            // warp's own-row params + row offsets from lane == warp
            const float cw  = __shfl_sync(0xffffffffu, c, warp);
            const float sw  = __shfl_sync(0xffffffffu, s, warp);
            const int   pwS = __shfl_sync(0xffffffffu, plS, warp);
            const int   qwS = __shfl_sync(0xffffffffu, qlS, warp);

            // ---- fused two-sided update of the 2x2 block ----
            const float* Arp = A + pwS;
            const float* Arq = A + qwS;
            const float a_pp = Arp[pl];
            const float a_pq = Arp[ql];
            const float a_qp = Arq[pl];
            const float a_qq = Arq[ql];

            const float rp_p = fmaf(cw, a_pp, -sw * a_qp);
            const float rp_q = fmaf(cw, a_pq, -sw * a_qq);
            const float rq_p = fmaf(sw, a_pp,  cw * a_qp);
            const float rq_q = fmaf(sw, a_pq,  cw * a_qq);

            float* Anp = An + pwS;
            float* Anq = An + qwS;
            Anp[pl] = fmaf(c, rp_p, -s * rp_q);
            Anp[ql] = fmaf(s, rp_p,  c * rp_q);
            Anq[pl] = fmaf(c, rq_p, -s * rq_q);
            Anq[ql] = fmaf(s, rq_p,  c * rq_q);

            // ---- Qt <- J^T Qt (rows pw,qw; warp-local) ----
            {
                float2* Qp = (float2*)(Qts + pwS) + lane;
                float2* Qq = (float2*)(Qts + qwS) + lane;
                const float2 qp = *Qp;
                const float2 qq = *Qq;
                *Qp = make_float2(fmaf(cw, qp.x, -sw * qq.x),
                                  fmaf(cw, qp.y, -sw * qq.y));
                *Qq = make_float2(fmaf(sw, qp.x, cw * qq.x),
                                  fmaf(sw, qp.y, cw * qq.y));
            }

            // ---- advance indices (+1 mod 63; lane 0 keeps pl = 63) ----
            if (lane) {
                pl  = (pl  == 62)       ? 0 : pl + 1;
                plS = (plS == 62 * STR) ? 0 : plS + STR;
            }
            ql  = (ql  == 62)       ? 0 : ql + 1;
            qlS = (qlS == 62 * STR) ? 0 : qlS + STR;

            __syncthreads();
            cur ^= 1;
        }

        // convergence check on current buffer
        if (sweep >= CHECK_FROM) {
            const float* A = bufs[cur];
            float off = 0.f;
            for (int e = tid; e < DIM * DIM; e += 1024) {
                const int i = e >> 6, j = e & 63;
                const float v = A[i * STR + j];
                off += (i != j) ? v * v : 0.f;
            }
            const float offt = block_reduce_sum(off, red, tid);
            if (offt < 1e-7f * frob2) break;
        }
    }

    const float* Acur = bufs[cur];
    float*       Psp  = bufs[cur ^ 1];   // spare buffer for P

    // ---- g(lambda) = sign(l)*sqrt(|l|) ----
    __syncthreads();
    if (tid < DIM) {
        const float lam = Acur[tid * STR + tid];
        gs[tid] = copysignf(sqrtf(fabsf(lam)), lam);
    }
    __syncthreads();

    // P[k][i] = g_k * Qt[k][i]
    for (int e = tid; e < DIM * DIM; e += 1024) {
        const int k = e >> 6, i = e & 63;
        Psp[k * STR + i] = gs[k] * Qts[k * STR + i];
    }
    __syncthreads();

    // sq[i][j] = sum_k P[k][i] * Qt[k][j], thread owns (i, j0..j0+3)
    const int i = tid >> 4;
    const int j0 = (tid & 15) * 4;
    float a0 = 0.f, a1 = 0.f, a2 = 0.f, a3 = 0.f;
#pragma unroll 4
    for (int k = 0; k < DIM; k++) {
        const float pki = Psp[k * STR + i];
        float2 qa = *(float2*)&Qts[k * STR + j0];
        float2 qb = *(float2*)&Qts[k * STR + j0 + 2];
        a0 += pki * qa.x;
        a1 += pki * qa.y;
        a2 += pki * qb.x;
        a3 += pki * qb.y;
    }

    // L2 normalize over all 4096 entries
    const float ssq = a0 * a0 + a1 * a1 + a2 * a2 + a3 * a3;
    const float total = block_reduce_sum(ssq, red, tid);
    const float scale = 1.f / fmaxf(sqrtf(total), 1e-12f);

    float4 v = make_float4(a0 * scale, a1 * scale, a2 * scale, a3 * scale);
    *(float4*)(out + (size_t)b * (DIM * DIM) + i * DIM + j0) = v;
}

// ---------------------------------------------------------------------------
extern "C" void kernel_launch(void* const* d_in, const int* in_sizes, int n_in,
                              void* d_out, int out_size) {
    const float* x = (const float*)d_in[0];
    float* out = (float*)d_out;

    cudaFuncSetAttribute(sop_eig_kernel,
                         cudaFuncAttributeMaxDynamicSharedMemorySize,
                         EIG_SMEM_BYTES);

    sop_partial_max<<<dim3(SPLIT, BATCH), 256>>>(x);
    sop_eig_kernel<<<BATCH, 1024, EIG_SMEM_BYTES>>>(out);
}

// round 5
// speedup vs baseline: 3.6717x; 1.2438x over previous
#include <cuda_runtime.h>
#include <math.h>
#include <float.h>

#define BATCH 16
#define NPTS  2048
#define DIM   64
#define SPLIT 16
#define ROWS_PER (NPTS / SPLIT)   // 128
#define STR 68                    // row stride: 68*4B = 272B, 16B-aligned rows
#define MAXSWEEP 9
#define CHECK_FROM 2
#define ETHREADS 512

#define EIG_SMEM_FLOATS (3 * DIM * STR)
#define EIG_SMEM_BYTES  (EIG_SMEM_FLOATS * 4)

// scratch for partial maxima: 16 * 16 * 4096 * 4B = 4 MB
__device__ float g_partial[BATCH][SPLIT][DIM * DIM];

// ---------------------------------------------------------------------------
// Kernel 1: partial max of outer products over a 128-row chunk of n
// ---------------------------------------------------------------------------
__global__ void __launch_bounds__(256) sop_partial_max(const float* __restrict__ x) {
    const int b = blockIdx.y;
    const int c = blockIdx.x;
    __shared__ float xs[ROWS_PER][DIM];

    const float* xp = x + ((size_t)b * NPTS + (size_t)c * ROWS_PER) * DIM;
    const int tid = threadIdx.x;

    for (int e = tid * 4; e < ROWS_PER * DIM; e += 256 * 4) {
        float4 v = *(const float4*)(xp + e);
        *(float4*)(&xs[0][0] + e) = v;
    }
    __syncthreads();

    const int ti = (tid >> 4) * 4;
    const int tj = (tid & 15) * 4;
    float acc[4][4];
#pragma unroll
    for (int a = 0; a < 4; a++)
#pragma unroll
        for (int bb = 0; bb < 4; bb++) acc[a][bb] = -FLT_MAX;

#pragma unroll 4
    for (int n = 0; n < ROWS_PER; n++) {
        float4 vi = *(const float4*)&xs[n][ti];
        float4 vj = *(const float4*)&xs[n][tj];
        float fi[4] = {vi.x, vi.y, vi.z, vi.w};
        float fj[4] = {vj.x, vj.y, vj.z, vj.w};
#pragma unroll
        for (int a = 0; a < 4; a++)
#pragma unroll
            for (int bb = 0; bb < 4; bb++)
                acc[a][bb] = fmaxf(acc[a][bb], fi[a] * fj[bb]);
    }

    float* outp = g_partial[b][c];
#pragma unroll
    for (int a = 0; a < 4; a++) {
        float4 v = make_float4(acc[a][0], acc[a][1], acc[a][2], acc[a][3]);
        *(float4*)(outp + (ti + a) * DIM + tj) = v;
    }
}

// ---------------------------------------------------------------------------
// block reduce sum for 512 threads / 16 warps
// ---------------------------------------------------------------------------
__device__ __forceinline__ float block_reduce_sum(float v, float* red, int tid) {
    __syncthreads();
#pragma unroll
    for (int o = 16; o; o >>= 1) v += __shfl_down_sync(0xffffffffu, v, o);
    if ((tid & 31) == 0) red[tid >> 5] = v;
    __syncthreads();
    if (tid < 32) {
        float w = (tid < 16) ? red[tid] : 0.f;
#pragma unroll
        for (int o = 8; o; o >>= 1) w += __shfl_down_sync(0xffffffffu, w, o);
        if (tid == 0) red[0] = w;
    }
    __syncthreads();
    return red[0];
}

// ---------------------------------------------------------------------------
// Kernel 2: per-batch eigendecomposition, one barrier per Jacobi round.
// 512 threads. Warp w owns row-pairs {w, w+16}; lane j owns column pair j.
// Qt round-update is half-warp float4 (lanes 0-15 -> rpA, 16-31 -> rpB).
// ---------------------------------------------------------------------------
__global__ void __launch_bounds__(ETHREADS) sop_eig_kernel(float* __restrict__ out) {
    extern __shared__ float dsm[];
    float* Abuf0 = dsm;
    float* Abuf1 = dsm + DIM * STR;
    float* Qts   = dsm + 2 * DIM * STR;

    __shared__ float red[16];
    __shared__ float gs[DIM];

    const int b = blockIdx.x;
    const int tid = threadIdx.x;
    const int warp = tid >> 5;
    const int lane = tid & 31;

    // ---- reduce partials into A0 (float4), init Qt = I ----
    float frloc = 0.f;
    {
        const int e0 = tid * 8;                 // 512*8 = 4096 exactly
        const int i = e0 >> 6, j0 = e0 & 63;
        float4 m0 = make_float4(-FLT_MAX, -FLT_MAX, -FLT_MAX, -FLT_MAX);
        float4 m1 = m0;
#pragma unroll
        for (int c = 0; c < SPLIT; c++) {
            const float4* gp = (const float4*)&g_partial[b][c][e0];
            float4 v0 = gp[0], v1 = gp[1];
            m0.x = fmaxf(m0.x, v0.x); m0.y = fmaxf(m0.y, v0.y);
            m0.z = fmaxf(m0.z, v0.z); m0.w = fmaxf(m0.w, v0.w);
            m1.x = fmaxf(m1.x, v1.x); m1.y = fmaxf(m1.y, v1.y);
            m1.z = fmaxf(m1.z, v1.z); m1.w = fmaxf(m1.w, v1.w);
        }
        *(float4*)&Abuf0[i * STR + j0]     = m0;
        *(float4*)&Abuf0[i * STR + j0 + 4] = m1;
        frloc = m0.x*m0.x + m0.y*m0.y + m0.z*m0.z + m0.w*m0.w
              + m1.x*m1.x + m1.y*m1.y + m1.z*m1.z + m1.w*m1.w;
        float4 id0 = make_float4((i == j0+0)?1.f:0.f, (i == j0+1)?1.f:0.f,
                                 (i == j0+2)?1.f:0.f, (i == j0+3)?1.f:0.f);
        float4 id1 = make_float4((i == j0+4)?1.f:0.f, (i == j0+5)?1.f:0.f,
                                 (i == j0+6)?1.f:0.f, (i == j0+7)?1.f:0.f);
        *(float4*)&Qts[i * STR + j0]     = id0;
        *(float4*)&Qts[i * STR + j0 + 4] = id1;
    }
    const float frob2 = block_reduce_sum(frloc, red, tid) + 1e-30f;
    // ends with __syncthreads -> A0/Qt visible

    // ---- persistent tournament indices for this lane's column pair ----
    int pl, ql;
    if (lane == 0) { pl = 63; ql = 0; }
    else           { pl = lane; ql = 63 - lane; }
    int plS = pl * STR;
    int qlS = ql * STR;

    float* Ac = Abuf0;
    float* An = Abuf1;

    for (int sweep = 0; sweep < MAXSWEEP; sweep++) {
        for (int r = 0; r < 63; r++) {
            // ---- rotation params for column pair 'lane' (2 MUFU) ----
            const float app = Ac[plS + pl];
            const float aqq = Ac[qlS + ql];
            const float apq = Ac[plS + ql];
            const float d = aqq - app;
            const float g = apq + apq;
            const float rr = fmaf(d, d, g * g);
            const float ir = __frsqrt_rn(rr);
            const float xv = fabsf(d) * ir;
            const float yv = fmaf(0.5f, xv, 0.5f);
            const float ic = __frsqrt_rn(yv);
            float c = yv * ic;
            float s = 0.5f * g * ir * ic;
            s = __int_as_float(__float_as_int(s) ^
                               (__float_as_int(d) & 0x80000000));
            if (rr < 1e-40f) { c = 1.f; s = 0.f; }

            // ---- row-pair params for rpA = warp, rpB = warp+16 ----
            const float cA  = __shfl_sync(0xffffffffu, c,   warp);
            const float sA  = __shfl_sync(0xffffffffu, s,   warp);
            const int   pSA = __shfl_sync(0xffffffffu, plS, warp);
            const int   qSA = __shfl_sync(0xffffffffu, qlS, warp);
            const float cB  = __shfl_sync(0xffffffffu, c,   warp + 16);
            const float sB  = __shfl_sync(0xffffffffu, s,   warp + 16);
            const int   pSB = __shfl_sync(0xffffffffu, plS, warp + 16);
            const int   qSB = __shfl_sync(0xffffffffu, qlS, warp + 16);

            // ---- A: fused two-sided 2x2 update, row-pair A ----
            {
                const float a_pp = Ac[pSA + pl];
                const float a_pq = Ac[pSA + ql];
                const float a_qp = Ac[qSA + pl];
                const float a_qq = Ac[qSA + ql];
                const float rp_p = fmaf(cA, a_pp, -sA * a_qp);
                const float rp_q = fmaf(cA, a_pq, -sA * a_qq);
                const float rq_p = fmaf(sA, a_pp,  cA * a_qp);
                const float rq_q = fmaf(sA, a_pq,  cA * a_qq);
                An[pSA + pl] = fmaf(c, rp_p, -s * rp_q);
                An[pSA + ql] = fmaf(s, rp_p,  c * rp_q);
                An[qSA + pl] = fmaf(c, rq_p, -s * rq_q);
                An[qSA + ql] = fmaf(s, rq_p,  c * rq_q);
            }
            // ---- A: row-pair B ----
            {
                const float a_pp = Ac[pSB + pl];
                const float a_pq = Ac[pSB + ql];
                const float a_qp = Ac[qSB + pl];
                const float a_qq = Ac[qSB + ql];
                const float rp_p = fmaf(cB, a_pp, -sB * a_qp);
                const float rp_q = fmaf(cB, a_pq, -sB * a_qq);
                const float rq_p = fmaf(sB, a_pp,  cB * a_qp);
                const float rq_q = fmaf(sB, a_pq,  cB * a_qq);
                An[pSB + pl] = fmaf(c, rp_p, -s * rp_q);
                An[pSB + ql] = fmaf(s, rp_p,  c * rp_q);
                An[qSB + pl] = fmaf(c, rq_p, -s * rq_q);
                An[qSB + ql] = fmaf(s, rq_p,  c * rq_q);
            }

            // ---- Qt <- J^T Qt: half-warp float4 (lanes<16 rpA, else rpB) ----
            {
                const float cq = (lane < 16) ? cA : cB;
                const float sq = (lane < 16) ? sA : sB;
                const int   pS = (lane < 16) ? pSA : pSB;
                const int   qS = (lane < 16) ? qSA : qSB;
                const int   sub = (lane & 15) * 4;
                float4* Qp = (float4*)(Qts + pS + sub);
                float4* Qq = (float4*)(Qts + qS + sub);
                const float4 qp = *Qp;
                const float4 qq = *Qq;
                *Qp = make_float4(fmaf(cq, qp.x, -sq * qq.x),
                                  fmaf(cq, qp.y, -sq * qq.y),
                                  fmaf(cq, qp.z, -sq * qq.z),
                                  fmaf(cq, qp.w, -sq * qq.w));
                *Qq = make_float4(fmaf(sq, qp.x, cq * qq.x),
                                  fmaf(sq, qp.y, cq * qq.y),
                                  fmaf(sq, qp.z, cq * qq.z),
                                  fmaf(sq, qp.w, cq * qq.w));
            }

            // ---- advance indices (+1 mod 63; lane 0 keeps pl = 63) ----
            if (lane) {
                pl  = (pl  == 62)       ? 0 : pl + 1;
                plS = (plS == 62 * STR) ? 0 : plS + STR;
            }
            ql  = (ql  == 62)       ? 0 : ql + 1;
            qlS = (qlS == 62 * STR) ? 0 : qlS + STR;

            __syncthreads();
            float* t = Ac; Ac = An; An = t;
        }

        // ---- convergence check ----
        if (sweep >= CHECK_FROM) {
            float off = 0.f;
            const int e0 = tid * 8;
            const int i = e0 >> 6, j0 = e0 & 63;
#pragma unroll
            for (int u = 0; u < 8; u++) {
                const float v = Ac[i * STR + j0 + u];
                off += (i != j0 + u) ? v * v : 0.f;
            }
            const float offt = block_reduce_sum(off, red, tid);
            if (offt < 1e-7f * frob2) break;
        }
    }

    float* Psp = An;   // spare buffer

    // ---- g(lambda) = sign(l)*sqrt(|l|) ----
    __syncthreads();
    if (tid < DIM) {
        const float lam = Ac[tid * STR + tid];
        gs[tid] = copysignf(sqrtf(fabsf(lam)), lam);
    }
    __syncthreads();

    // P[k][i] = g_k * Qt[k][i]
    {
        const int e0 = tid * 8;
        const int k = e0 >> 6, i0 = e0 & 63;
        const float gk = gs[k];
        float4 q0 = *(float4*)&Qts[k * STR + i0];
        float4 q1 = *(float4*)&Qts[k * STR + i0 + 4];
        q0.x *= gk; q0.y *= gk; q0.z *= gk; q0.w *= gk;
        q1.x *= gk; q1.y *= gk; q1.z *= gk; q1.w *= gk;
        *(float4*)&Psp[k * STR + i0]     = q0;
        *(float4*)&Psp[k * STR + i0 + 4] = q1;
    }
    __syncthreads();

    // sq[i][j] = sum_k P[k][i] * Qt[k][j]; thread owns (i, j0..j0+7)
    const int i = tid >> 3;
    const int j0 = (tid & 7) * 8;
    float4 acc0 = make_float4(0.f, 0.f, 0.f, 0.f);
    float4 acc1 = acc0;
#pragma unroll 4
    for (int k = 0; k < DIM; k++) {
        const float pki = Psp[k * STR + i];
        const float4 qa = *(const float4*)&Qts[k * STR + j0];
        const float4 qb = *(const float4*)&Qts[k * STR + j0 + 4];
        acc0.x = fmaf(pki, qa.x, acc0.x);
        acc0.y = fmaf(pki, qa.y, acc0.y);
        acc0.z = fmaf(pki, qa.z, acc0.z);
        acc0.w = fmaf(pki, qa.w, acc0.w);
        acc1.x = fmaf(pki, qb.x, acc1.x);
        acc1.y = fmaf(pki, qb.y, acc1.y);
        acc1.z = fmaf(pki, qb.z, acc1.z);
        acc1.w = fmaf(pki, qb.w, acc1.w);
    }

    // L2 normalize over all 4096 entries
    const float ssq = acc0.x*acc0.x + acc0.y*acc0.y + acc0.z*acc0.z + acc0.w*acc0.w
                    + acc1.x*acc1.x + acc1.y*acc1.y + acc1.z*acc1.z + acc1.w*acc1.w;
    const float total = block_reduce_sum(ssq, red, tid);
    const float scale = 1.f / fmaxf(sqrtf(total), 1e-12f);

    acc0.x *= scale; acc0.y *= scale; acc0.z *= scale; acc0.w *= scale;
    acc1.x *= scale; acc1.y *= scale; acc1.z *= scale; acc1.w *= scale;
    float* op = out + (size_t)b * (DIM * DIM) + i * DIM + j0;
    *(float4*)op       = acc0;
    *(float4*)(op + 4) = acc1;
}

// ---------------------------------------------------------------------------
extern "C" void kernel_launch(void* const* d_in, const int* in_sizes, int n_in,
                              void* d_out, int out_size) {
    const float* x = (const float*)d_in[0];
    float* out = (float*)d_out;

    cudaFuncSetAttribute(sop_eig_kernel,
                         cudaFuncAttributeMaxDynamicSharedMemorySize,
                         EIG_SMEM_BYTES);

    sop_partial_max<<<dim3(SPLIT, BATCH), 256>>>(x);
    sop_eig_kernel<<<BATCH, ETHREADS, EIG_SMEM_BYTES>>>(out);
}

// round 6
// speedup vs baseline: 4.1649x; 1.1343x over previous
#include <cuda_runtime.h>
#include <math.h>
#include <float.h>

#define BATCH 16
#define NPTS  2048
#define DIM   64
#define SPLIT 16
#define ROWS_PER (NPTS / SPLIT)   // 128
#define STR 68                    // row stride: 16B-aligned rows
#define ETHREADS 512

#define EIG_SMEM_FLOATS (3 * DIM * STR)
#define EIG_SMEM_BYTES  (EIG_SMEM_FLOATS * 4)

// scratch for partial maxima: 16 * 16 * 4096 * 4B = 4 MB
__device__ float g_partial[BATCH][SPLIT][DIM * DIM];

// ---------------------------------------------------------------------------
// Kernel 1: partial max of outer products over a 128-row chunk of n
// ---------------------------------------------------------------------------
__global__ void __launch_bounds__(256) sop_partial_max(const float* __restrict__ x) {
    const int b = blockIdx.y;
    const int c = blockIdx.x;
    __shared__ float xs[ROWS_PER][DIM];

    const float* xp = x + ((size_t)b * NPTS + (size_t)c * ROWS_PER) * DIM;
    const int tid = threadIdx.x;

    for (int e = tid * 4; e < ROWS_PER * DIM; e += 256 * 4) {
        float4 v = *(const float4*)(xp + e);
        *(float4*)(&xs[0][0] + e) = v;
    }
    __syncthreads();

    const int ti = (tid >> 4) * 4;
    const int tj = (tid & 15) * 4;
    float acc[4][4];
#pragma unroll
    for (int a = 0; a < 4; a++)
#pragma unroll
        for (int bb = 0; bb < 4; bb++) acc[a][bb] = -FLT_MAX;

#pragma unroll 4
    for (int n = 0; n < ROWS_PER; n++) {
        float4 vi = *(const float4*)&xs[n][ti];
        float4 vj = *(const float4*)&xs[n][tj];
        float fi[4] = {vi.x, vi.y, vi.z, vi.w};
        float fj[4] = {vj.x, vj.y, vj.z, vj.w};
#pragma unroll
        for (int a = 0; a < 4; a++)
#pragma unroll
            for (int bb = 0; bb < 4; bb++)
                acc[a][bb] = fmaxf(acc[a][bb], fi[a] * fj[bb]);
    }

    float* outp = g_partial[b][c];
#pragma unroll
    for (int a = 0; a < 4; a++) {
        float4 v = make_float4(acc[a][0], acc[a][1], acc[a][2], acc[a][3]);
        *(float4*)(outp + (ti + a) * DIM + tj) = v;
    }
}

// ---------------------------------------------------------------------------
__device__ __forceinline__ float block_reduce_sum(float v, float* red, int tid) {
    __syncthreads();
#pragma unroll
    for (int o = 16; o; o >>= 1) v += __shfl_down_sync(0xffffffffu, v, o);
    if ((tid & 31) == 0) red[tid >> 5] = v;
    __syncthreads();
    if (tid < 32) {
        float w = (tid < 16) ? red[tid] : 0.f;
#pragma unroll
        for (int o = 8; o; o >>= 1) w += __shfl_down_sync(0xffffffffu, w, o);
        if (tid == 0) red[0] = w;
    }
    __syncthreads();
    return red[0];
}

// ---------------------------------------------------------------------------
// Kernel 2: 4 Jacobi sweeps (+optional 5th), then Daleckii-Krein first-order
// matrix-sqrt correction + Qt^T F Qt reconstruction + L2 normalize.
// 512 threads. Warp w owns row-pairs {w, w+16}; lane j owns column pair j.
// ---------------------------------------------------------------------------
__global__ void __launch_bounds__(ETHREADS) sop_eig_kernel(float* __restrict__ out) {
    extern __shared__ float dsm[];
    float* Abuf0 = dsm;
    float* Abuf1 = dsm + DIM * STR;
    float* Qts   = dsm + 2 * DIM * STR;

    __shared__ float red[16];
    __shared__ float gs[DIM];

    const int b = blockIdx.x;
    const int tid = threadIdx.x;
    const int warp = tid >> 5;
    const int lane = tid & 31;

    // ---- reduce partials into A0 (float4), init Qt = I ----
    float frloc = 0.f;
    {
        const int e0 = tid * 8;
        const int i = e0 >> 6, j0 = e0 & 63;
        float4 m0 = make_float4(-FLT_MAX, -FLT_MAX, -FLT_MAX, -FLT_MAX);
        float4 m1 = m0;
#pragma unroll
        for (int c = 0; c < SPLIT; c++) {
            const float4* gp = (const float4*)&g_partial[b][c][e0];
            float4 v0 = gp[0], v1 = gp[1];
            m0.x = fmaxf(m0.x, v0.x); m0.y = fmaxf(m0.y, v0.y);
            m0.z = fmaxf(m0.z, v0.z); m0.w = fmaxf(m0.w, v0.w);
            m1.x = fmaxf(m1.x, v1.x); m1.y = fmaxf(m1.y, v1.y);
            m1.z = fmaxf(m1.z, v1.z); m1.w = fmaxf(m1.w, v1.w);
        }
        *(float4*)&Abuf0[i * STR + j0]     = m0;
        *(float4*)&Abuf0[i * STR + j0 + 4] = m1;
        frloc = m0.x*m0.x + m0.y*m0.y + m0.z*m0.z + m0.w*m0.w
              + m1.x*m1.x + m1.y*m1.y + m1.z*m1.z + m1.w*m1.w;
        float4 id0 = make_float4((i == j0+0)?1.f:0.f, (i == j0+1)?1.f:0.f,
                                 (i == j0+2)?1.f:0.f, (i == j0+3)?1.f:0.f);
        float4 id1 = make_float4((i == j0+4)?1.f:0.f, (i == j0+5)?1.f:0.f,
                                 (i == j0+6)?1.f:0.f, (i == j0+7)?1.f:0.f);
        *(float4*)&Qts[i * STR + j0]     = id0;
        *(float4*)&Qts[i * STR + j0 + 4] = id1;
    }
    const float frob2 = block_reduce_sum(frloc, red, tid) + 1e-30f;

    // ---- persistent tournament indices for this lane's column pair ----
    int pl, ql;
    if (lane == 0) { pl = 63; ql = 0; }
    else           { pl = lane; ql = 63 - lane; }
    int plS = pl * STR;
    int qlS = ql * STR;

    float* Ac = Abuf0;
    float* An = Abuf1;

    for (int sweep = 0; sweep < 5; sweep++) {
        // after 4 sweeps: run 5th only if off-diagonal mass still too large for DK
        if (sweep == 4) {
            float off = 0.f;
            const int e0 = tid * 8;
            const int i = e0 >> 6, j0 = e0 & 63;
#pragma unroll
            for (int u = 0; u < 8; u++) {
                const float v = Ac[i * STR + j0 + u];
                off += (i != j0 + u) ? v * v : 0.f;
            }
            const float offt = block_reduce_sum(off, red, tid);
            if (offt < 3e-5f * frob2) break;
        }

        for (int r = 0; r < 63; r++) {
            // ---- rotation params for column pair 'lane' (2 MUFU) ----
            const float app = Ac[plS + pl];
            const float aqq = Ac[qlS + ql];
            const float apq = Ac[plS + ql];
            const float d = aqq - app;
            const float g = apq + apq;
            const float rr = fmaf(d, d, g * g);
            const float ir = __frsqrt_rn(rr);
            const float xv = fabsf(d) * ir;
            const float yv = fmaf(0.5f, xv, 0.5f);
            const float ic = __frsqrt_rn(yv);
            float c = yv * ic;
            float s = 0.5f * g * ir * ic;
            s = __int_as_float(__float_as_int(s) ^
                               (__float_as_int(d) & 0x80000000));
            if (rr < 1e-40f) { c = 1.f; s = 0.f; }

            // ---- row-pair params for rpA = warp, rpB = warp+16 ----
            const float cA  = __shfl_sync(0xffffffffu, c,   warp);
            const float sA  = __shfl_sync(0xffffffffu, s,   warp);
            const int   pSA = __shfl_sync(0xffffffffu, plS, warp);
            const int   qSA = __shfl_sync(0xffffffffu, qlS, warp);
            const float cB  = __shfl_sync(0xffffffffu, c,   warp + 16);
            const float sB  = __shfl_sync(0xffffffffu, s,   warp + 16);
            const int   pSB = __shfl_sync(0xffffffffu, plS, warp + 16);
            const int   qSB = __shfl_sync(0xffffffffu, qlS, warp + 16);

            // ---- A: fused two-sided 2x2 update, row-pair A ----
            {
                const float a_pp = Ac[pSA + pl];
                const float a_pq = Ac[pSA + ql];
                const float a_qp = Ac[qSA + pl];
                const float a_qq = Ac[qSA + ql];
                const float rp_p = fmaf(cA, a_pp, -sA * a_qp);
                const float rp_q = fmaf(cA, a_pq, -sA * a_qq);
                const float rq_p = fmaf(sA, a_pp,  cA * a_qp);
                const float rq_q = fmaf(sA, a_pq,  cA * a_qq);
                An[pSA + pl] = fmaf(c, rp_p, -s * rp_q);
                An[pSA + ql] = fmaf(s, rp_p,  c * rp_q);
                An[qSA + pl] = fmaf(c, rq_p, -s * rq_q);
                An[qSA + ql] = fmaf(s, rq_p,  c * rq_q);
            }
            // ---- A: row-pair B ----
            {
                const float a_pp = Ac[pSB + pl];
                const float a_pq = Ac[pSB + ql];
                const float a_qp = Ac[qSB + pl];
                const float a_qq = Ac[qSB + ql];
                const float rp_p = fmaf(cB, a_pp, -sB * a_qp);
                const float rp_q = fmaf(cB, a_pq, -sB * a_qq);
                const float rq_p = fmaf(sB, a_pp,  cB * a_qp);
                const float rq_q = fmaf(sB, a_pq,  cB * a_qq);
                An[pSB + pl] = fmaf(c, rp_p, -s * rp_q);
                An[pSB + ql] = fmaf(s, rp_p,  c * rp_q);
                An[qSB + pl] = fmaf(c, rq_p, -s * rq_q);
                An[qSB + ql] = fmaf(s, rq_p,  c * rq_q);
            }

            // ---- Qt <- J^T Qt: half-warp float4 ----
            {
                const float cq = (lane < 16) ? cA : cB;
                const float sq = (lane < 16) ? sA : sB;
                const int   pS = (lane < 16) ? pSA : pSB;
                const int   qS = (lane < 16) ? qSA : qSB;
                const int   sub = (lane & 15) * 4;
                float4* Qp = (float4*)(Qts + pS + sub);
                float4* Qq = (float4*)(Qts + qS + sub);
                const float4 qp = *Qp;
                const float4 qq = *Qq;
                *Qp = make_float4(fmaf(cq, qp.x, -sq * qq.x),
                                  fmaf(cq, qp.y, -sq * qq.y),
                                  fmaf(cq, qp.z, -sq * qq.z),
                                  fmaf(cq, qp.w, -sq * qq.w));
                *Qq = make_float4(fmaf(sq, qp.x, cq * qq.x),
                                  fmaf(sq, qp.y, cq * qq.y),
                                  fmaf(sq, qp.z, cq * qq.z),
                                  fmaf(sq, qp.w, cq * qq.w));
            }

            // ---- advance indices (+1 mod 63; lane 0 keeps pl = 63) ----
            if (lane) {
                pl  = (pl  == 62)       ? 0 : pl + 1;
                plS = (plS == 62 * STR) ? 0 : plS + STR;
            }
            ql  = (ql  == 62)       ? 0 : ql + 1;
            qlS = (qlS == 62 * STR) ? 0 : qlS + STR;

            __syncthreads();
            float* t = Ac; Ac = An; An = t;
        }
    }

    // =======================================================================
    // Daleckii-Krein first-order matrix sqrt of A = D + E (nearly diagonal):
    //   F_ii = g(d_i);  F_ij = E_ij * (g_i - g_j)/(d_i - d_j)
    //   msqrt = Qt^T F Qt
    // =======================================================================

    // g(lambda) for the diagonal
    __syncthreads();
    if (tid < DIM) {
        const float lam = Ac[tid * STR + tid];
        gs[tid] = copysignf(sqrtf(fabsf(lam)), lam);
    }
    __syncthreads();

    // build F into An
    {
        const int e0 = tid * 8;
        const int i = e0 >> 6, j0 = e0 & 63;
        const float gi = gs[i];
        const float di = gi * fabsf(gi);
#pragma unroll
        for (int u = 0; u < 8; u++) {
            const int j = j0 + u;
            const float gj = gs[j];
            const float dj = gj * fabsf(gj);
            float DD;
            if ((__float_as_int(gi) ^ __float_as_int(gj)) >= 0) {
                // same sign: stable closed form 1/(|gi|+|gj|)
                DD = __fdividef(1.f, fabsf(gi) + fabsf(gj) + 1e-12f);
            } else {
                // opposite sign: |di - dj| = |di|+|dj|, well separated
                const float den = di - dj;
                DD = __fdividef(gi - gj, den + copysignf(1e-12f, den));
            }
            An[i * STR + j] = (i == j) ? gi : Ac[i * STR + j] * DD;
        }
    }
    __syncthreads();

    // GEMM1: T[k][j] = sum_l F[k][l] * Qt[l][j]   (T -> Ac buffer)
    {
        const int k = tid >> 3;
        const int j0 = (tid & 7) * 8;
        float4 t0 = make_float4(0.f, 0.f, 0.f, 0.f);
        float4 t1 = t0;
#pragma unroll 4
        for (int l = 0; l < DIM; l++) {
            const float fkl = An[k * STR + l];
            const float4 qa = *(const float4*)&Qts[l * STR + j0];
            const float4 qb = *(const float4*)&Qts[l * STR + j0 + 4];
            t0.x = fmaf(fkl, qa.x, t0.x);
            t0.y = fmaf(fkl, qa.y, t0.y);
            t0.z = fmaf(fkl, qa.z, t0.z);
            t0.w = fmaf(fkl, qa.w, t0.w);
            t1.x = fmaf(fkl, qb.x, t1.x);
            t1.y = fmaf(fkl, qb.y, t1.y);
            t1.z = fmaf(fkl, qb.z, t1.z);
            t1.w = fmaf(fkl, qb.w, t1.w);
        }
        __syncthreads();   // everyone done reading Ac (via gs) long ago; F reads done
        *(float4*)&Ac[k * STR + j0]     = t0;
        *(float4*)&Ac[k * STR + j0 + 4] = t1;
    }
    __syncthreads();

    // GEMM2: sq[i][j] = sum_k Qt[k][i] * T[k][j]
    const int i = tid >> 3;
    const int j0 = (tid & 7) * 8;
    float4 acc0 = make_float4(0.f, 0.f, 0.f, 0.f);
    float4 acc1 = acc0;
#pragma unroll 4
    for (int k = 0; k < DIM; k++) {
        const float qki = Qts[k * STR + i];
        const float4 ta = *(const float4*)&Ac[k * STR + j0];
        const float4 tb = *(const float4*)&Ac[k * STR + j0 + 4];
        acc0.x = fmaf(qki, ta.x, acc0.x);
        acc0.y = fmaf(qki, ta.y, acc0.y);
        acc0.z = fmaf(qki, ta.z, acc0.z);
        acc0.w = fmaf(qki, ta.w, acc0.w);
        acc1.x = fmaf(qki, tb.x, acc1.x);
        acc1.y = fmaf(qki, tb.y, acc1.y);
        acc1.z = fmaf(qki, tb.z, acc1.z);
        acc1.w = fmaf(qki, tb.w, acc1.w);
    }

    // L2 normalize over all 4096 entries
    const float ssq = acc0.x*acc0.x + acc0.y*acc0.y + acc0.z*acc0.z + acc0.w*acc0.w
                    + acc1.x*acc1.x + acc1.y*acc1.y + acc1.z*acc1.z + acc1.w*acc1.w;
    const float total = block_reduce_sum(ssq, red, tid);
    const float scale = 1.f / fmaxf(sqrtf(total), 1e-12f);

    acc0.x *= scale; acc0.y *= scale; acc0.z *= scale; acc0.w *= scale;
    acc1.x *= scale; acc1.y *= scale; acc1.z *= scale; acc1.w *= scale;
    float* op = out + (size_t)b * (DIM * DIM) + i * DIM + j0;
    *(float4*)op       = acc0;
    *(float4*)(op + 4) = acc1;
}

// ---------------------------------------------------------------------------
extern "C" void kernel_launch(void* const* d_in, const int* in_sizes, int n_in,
                              void* d_out, int out_size) {
    const float* x = (const float*)d_in[0];
    float* out = (float*)d_out;

    cudaFuncSetAttribute(sop_eig_kernel,
                         cudaFuncAttributeMaxDynamicSharedMemorySize,
                         EIG_SMEM_BYTES);

    sop_partial_max<<<dim3(SPLIT, BATCH), 256>>>(x);
    sop_eig_kernel<<<BATCH, ETHREADS, EIG_SMEM_BYTES>>>(out);
}